// round 9
// baseline (speedup 1.0000x reference)
#include <cuda_runtime.h>
#include <cuda_fp16.h>
#include <math.h>
#include <stddef.h>
#include <stdint.h>

// ---------------- problem constants ----------------
constexpr int BB   = 8;
constexpr int TT   = 16;
constexpr int NN   = 256;
constexpr int CB   = 1024;
constexpr int HH   = 16;
constexpr int HDD  = 64;
constexpr int KEXP = 8;
constexpr int BTT  = BB * TT;          // 128
constexpr int MROWS = BTT * NN;        // 32768
constexpr float EPS = 1e-5f;
constexpr size_t QK = (size_t)MROWS * CB;   // per-batch stride q/k
constexpr size_t WNS = (size_t)CB * CB;

// ---------------- device scratch ----------------
__device__ __align__(128) float g_qsum[KEXP * CB];
__device__ __align__(128) float g_ksum[KEXP * CB];
__device__ __align__(128) float g_dyn[BB * NN * KEXP];
__device__ __align__(128) float g_qscale[BB * NN * CB];
__device__ __align__(128) float g_kscale[BB * NN * CB];
__device__ __align__(128) float g_bc[CB];

__device__ __align__(128) __half g_xh  [QK];
__device__ __align__(128) __half g_qkh [2 * QK];      // q then k (scaled splits)
__device__ __align__(128) __half g_qkl [2 * QK];
__device__ __align__(128) __half g_qpkh[2 * QK];      // qp then kp
__device__ __align__(128) __half g_qpkl[2 * QK];
__device__ __align__(128) __half g_vpth[QK];          // vp transposed per bt: [bt][d][key]
__device__ __align__(128) __half g_cxh [QK];
__device__ __align__(128) __half g_cxl [QK];
__device__ __align__(128) __half g_ah  [(size_t)BTT * HH * NN * NN];   // probs fp16

__device__ __align__(128) __half w_qkh [2 * WNS];     // wq,wk splits
__device__ __align__(128) __half w_qkl [2 * WNS];
__device__ __align__(128) __half w_wvh [WNS];
__device__ __align__(128) __half w_wvl [WNS];
__device__ __align__(128) __half w_vwth[WNS];
__device__ __align__(128) __half w_vwtl[WNS];
__device__ __align__(128) __half w_wch [WNS];
__device__ __align__(128) __half w_wcl [WNS];
__device__ __align__(128) __half w_owh [WNS];

// ---------------- helpers ----------------
__device__ __forceinline__ uint32_t smem_u32(const void* p) {
    return (uint32_t)__cvta_generic_to_shared(p);
}
__device__ __forceinline__ uint32_t sw128(uint32_t o) { return o ^ ((o >> 3) & 0x70); }
__device__ __forceinline__ float hfr(float a) { return __half2float(__float2half_rn(a)); }
__device__ __forceinline__ void ldsm_x4(uint32_t& r0, uint32_t& r1, uint32_t& r2, uint32_t& r3,
                                        uint32_t addr) {
    asm volatile("ldmatrix.sync.aligned.m8n8.x4.shared.b16 {%0,%1,%2,%3}, [%4];"
                 : "=r"(r0), "=r"(r1), "=r"(r2), "=r"(r3) : "r"(addr));
}
__device__ __forceinline__ void mma16816(float* d, const uint32_t* a, uint32_t b0, uint32_t b1) {
    asm volatile("mma.sync.aligned.m16n8k16.row.col.f32.f16.f16.f32 "
                 "{%0,%1,%2,%3}, {%4,%5,%6,%7}, {%8,%9}, {%0,%1,%2,%3};"
                 : "+f"(d[0]), "+f"(d[1]), "+f"(d[2]), "+f"(d[3])
                 : "r"(a[0]), "r"(a[1]), "r"(a[2]), "r"(a[3]), "r"(b0), "r"(b1));
}
__device__ __forceinline__ void cp16(uint32_t dst, const void* src) {
    asm volatile("cp.async.cg.shared.global [%0], [%1], 16;" :: "r"(dst), "l"(src) : "memory");
}
__device__ __forceinline__ void cp_commit() { asm volatile("cp.async.commit_group;" ::: "memory"); }
template<int N> __device__ __forceinline__ void cp_wait() {
    asm volatile("cp.async.wait_group %0;" :: "n"(N) : "memory");
}

// ---------------- fp16 split HMMA GEMM (plain NT), 3-stage cp.async pipeline ----------------
// NPROD=3: (A0+A1)@(B0+B1) via hh,hl,lh.  NPROD=2: (A0+A1)@B0 via hh,lh.
// OMODE 0: row-major out (Cf fp32 and/or Ch/Cl split2), bias per COL, optional resid.
//          supports gridDim.z batching with strides az (A,C), bz (B), bias += z*CB.
// OMODE 2: vpT write — out[col>>8][row][col&255] half (Ch only), bias per ROW.
template<int NPROD, int OMODE>
__global__ void __launch_bounds__(256)
hmma_f16(const __half* __restrict__ A0, const __half* __restrict__ A1,
         const __half* __restrict__ B0, const __half* __restrict__ B1,
         float* __restrict__ Cf, __half* __restrict__ Ch, __half* __restrict__ Cl,
         int Kdim, int lda, int ldb, int ldc,
         const float* __restrict__ bias, const float* __restrict__ resid,
         size_t az, size_t bz)
{
    constexpr int NSA = 2;
    constexpr int NSB = (NPROD == 3) ? 2 : 1;
    constexpr int ATILE = 128 * 64 * 2;
    constexpr int BTILE = 128 * 64 * 2;
    constexpr int STAGE = NSA * ATILE + NSB * BTILE;

    extern __shared__ char dsm[];
    const uint32_t sraw  = smem_u32(dsm);
    const uint32_t sbase = (sraw + 127u) & ~127u;

    const int tid  = threadIdx.x;
    const int wid  = tid >> 5;
    const int lane = tid & 31;
    const int wm   = wid & 3;
    const int wn   = wid >> 2;

    if (OMODE == 0 && blockIdx.z) {
        size_t zo = blockIdx.z * az, zb = blockIdx.z * bz;
        A0 += zo; A1 += zo; B0 += zb; if (B1) B1 += zb;
        if (Cf) Cf += zo;
        if (Ch) { Ch += zo; Cl += zo; }
        if (bias) bias += blockIdx.z * CB;
    }

    const __half* Ap[2] = {A0, A1};
    const __half* Bp[2] = {B0, B1};
    const int bm = blockIdx.y * 128, bn = blockIdx.x * 128;

    auto issue = [&](int s, int kt) {
        uint32_t st = sbase + s * STAGE;
        #pragma unroll
        for (int p = 0; p < NSA; p++) {
            const __half* As = Ap[p];
            #pragma unroll
            for (int r = 0; r < 4; r++) {
                int i = tid + r * 256;
                int row = i >> 3, ch = (i & 7) * 16;
                cp16(st + p * ATILE + sw128((uint32_t)(row * 128 + ch)),
                     (const char*)(As + (size_t)(bm + row) * lda + kt) + ch);
            }
        }
        #pragma unroll
        for (int p = 0; p < NSB; p++) {
            const __half* Bs = Bp[p];
            #pragma unroll
            for (int r = 0; r < 4; r++) {
                int i = tid + r * 256;
                int row = i >> 3, ch = (i & 7) * 16;
                cp16(st + NSA * ATILE + p * BTILE + sw128((uint32_t)(row * 128 + ch)),
                     (const char*)(Bs + (size_t)(bn + row) * ldb + kt) + ch);
            }
        }
        cp_commit();
    };

    float acc[2][8][4];
    #pragma unroll
    for (int mt = 0; mt < 2; mt++)
        #pragma unroll
        for (int nt = 0; nt < 8; nt++)
            #pragma unroll
            for (int j = 0; j < 4; j++) acc[mt][nt][j] = 0.f;

    const uint32_t a_roff = (uint32_t)((wm * 32 + (lane & 15)) * 128 + ((lane >> 4) << 4));
    const uint32_t b_roff = (uint32_t)((wn * 64 + ((lane >> 4) << 3) + (lane & 7)) * 128
                                       + (((lane >> 3) & 1) << 4));

    auto compute = [&](int s) {
        uint32_t st = sbase + s * STAGE;
        #pragma unroll
        for (int p = 0; p < NPROD; p++) {
            int pa, pb;
            if (NPROD == 3) { pa = (p == 2) ? 1 : 0; pb = (p == 1) ? 1 : 0; }
            else            { pa = p; pb = 0; }
            uint32_t abp = st + pa * ATILE;
            uint32_t bbp = st + NSA * ATILE + pb * BTILE;
            #pragma unroll
            for (int ks = 0; ks < 4; ks++) {
                uint32_t a[2][4];
                #pragma unroll
                for (int mt = 0; mt < 2; mt++)
                    ldsm_x4(a[mt][0], a[mt][1], a[mt][2], a[mt][3],
                            abp + sw128(a_roff + mt * 16 * 128 + ks * 32));
                #pragma unroll
                for (int bp = 0; bp < 4; bp++) {
                    uint32_t b0, b1, b2, b3;
                    ldsm_x4(b0, b1, b2, b3, bbp + sw128(b_roff + bp * 16 * 128 + ks * 32));
                    #pragma unroll
                    for (int mt = 0; mt < 2; mt++) {
                        mma16816(acc[mt][2 * bp],     a[mt], b0, b1);
                        mma16816(acc[mt][2 * bp + 1], a[mt], b2, b3);
                    }
                }
            }
        }
    };

    const int nch = Kdim / 64;
    issue(0, 0);
    if (nch > 1) issue(1, 64);
    if (nch > 2) issue(2, 128);
    for (int t = 0; t < nch; t++) {
        int rem = nch - 1 - t;
        if (rem >= 2) cp_wait<2>();
        else if (rem == 1) cp_wait<1>();
        else cp_wait<0>();
        __syncthreads();
        compute(t % 3);
        __syncthreads();
        if (t + 3 < nch) issue(t % 3, (t + 3) * 64);
    }

    // ---- epilogue ----
    #pragma unroll
    for (int mt = 0; mt < 2; mt++) {
        int r0 = bm + wm * 32 + mt * 16 + (lane >> 2);
        #pragma unroll
        for (int nt = 0; nt < 8; nt++) {
            int col = bn + wn * 64 + nt * 8 + (lane & 3) * 2;
            #pragma unroll
            for (int rr = 0; rr < 2; rr++) {
                int row = r0 + rr * 8;
                float v0 = acc[mt][nt][2 * rr];
                float v1 = acc[mt][nt][2 * rr + 1];
                if (OMODE == 2) {
                    float b = bias[row];
                    v0 += b; v1 += b;
                    size_t t0 = (size_t)(col >> 8) * (CB * NN) + (size_t)row * NN + (col & 255);
                    *(__half2*)(Ch + t0) = __floats2half2_rn(v0, v1);
                } else {
                    if (bias)  { v0 += bias[col]; v1 += bias[col + 1]; }
                    if (resid) {
                        const float* rp = resid + (size_t)row * ldc + col;
                        v0 += rp[0]; v1 += rp[1];
                    }
                    size_t base = (size_t)row * ldc + col;
                    if (Cf) *(float2*)(Cf + base) = make_float2(v0, v1);
                    if (Ch) {
                        float h0 = hfr(v0), h1 = hfr(v1);
                        *(__half2*)(Ch + base) = __floats2half2_rn(h0, h1);
                        *(__half2*)(Cl + base) = __floats2half2_rn(v0 - h0, v1 - h1);
                    }
                }
            }
        }
    }
}

// ---------------- flash attention: scores + softmax + PV fused ----------------
// grid (2 m-blocks, BT*H). 128 q-rows x 256 keys x 64 hd per block.
// Phase 1: scores (NP3). Phase 2: softmax -> fp16 probs to gmem + smem P-tile.
// Phase 3: PV (NP1, P from smem) — no accS/accPV register coexistence.
__global__ void __launch_bounds__(256)
flash_kernel(const __half* __restrict__ qph, const __half* __restrict__ qpl,
             const __half* __restrict__ kph, const __half* __restrict__ kpl,
             const __half* __restrict__ vpt,
             __half* __restrict__ AH, __half* __restrict__ cxh, __half* __restrict__ cxl)
{
    // smem phase1: [0,32K) qp splits | [32K,96K) kp splits | [96K,128K) V 4 chunks
    // smem phase2: [0,64K) P 4 chunks | red at [64K,65K) | V stays [96K,128K)
    extern __shared__ char dsm[];
    const uint32_t sraw = smem_u32(dsm);
    const uint32_t sb   = (sraw + 127u) & ~127u;
    char* const ab      = dsm + (sb - sraw);

    const int tid = threadIdx.x, wid = tid >> 5, lane = tid & 31;
    const int wm = wid & 3, wn = wid >> 2;
    const int z = blockIdx.y;
    const int bt = z >> 4, head = z & 15;
    const int bm = blockIdx.x * 128;

    const size_t qoff = (size_t)bt * NN * CB + (size_t)head * HDD;
    const size_t voff = (size_t)bt * CB * NN + (size_t)head * HDD * NN;

    // ---- load all operands ----
    {
        const __half* qs[2] = {qph, qpl};
        #pragma unroll
        for (int p = 0; p < 2; p++)
            #pragma unroll
            for (int r = 0; r < 4; r++) {
                int i = tid + r * 256;
                int row = i >> 3, ch = (i & 7) * 16;
                cp16(sb + p * 16384 + sw128((uint32_t)(row * 128 + ch)),
                     (const char*)(qs[p] + qoff + (size_t)(bm + row) * CB) + ch);
            }
        const __half* ks[2] = {kph, kpl};
        #pragma unroll
        for (int p = 0; p < 2; p++)
            #pragma unroll
            for (int r = 0; r < 8; r++) {
                int i = tid + r * 256;
                int row = i >> 3, ch = (i & 7) * 16;
                cp16(sb + 32768 + p * 32768 + sw128((uint32_t)(row * 128 + ch)),
                     (const char*)(ks[p] + qoff + (size_t)row * CB) + ch);
            }
        #pragma unroll
        for (int c = 0; c < 4; c++)
            #pragma unroll
            for (int r = 0; r < 2; r++) {
                int i = tid + r * 256;
                int row = i >> 3, ch = (i & 7) * 16;
                cp16(sb + 98304 + c * 8192 + sw128((uint32_t)(row * 128 + ch)),
                     (const char*)(vpt + voff + (size_t)row * NN + c * 64) + ch);
            }
        cp_commit();
        cp_wait<0>();
        __syncthreads();
    }

    // ---- phase 1: scores S = qp @ kp^T (NP3), 128 x 256 ----
    float accS[2][16][4];
    #pragma unroll
    for (int mt = 0; mt < 2; mt++)
        #pragma unroll
        for (int nt = 0; nt < 16; nt++)
            #pragma unroll
            for (int j = 0; j < 4; j++) accS[mt][nt][j] = 0.f;

    const uint32_t a_roff = (uint32_t)((wm * 32 + (lane & 15)) * 128 + ((lane >> 4) << 4));
    const uint32_t b_roff = (uint32_t)((wn * 128 + ((lane >> 4) << 3) + (lane & 7)) * 128
                                       + (((lane >> 3) & 1) << 4));
    #pragma unroll
    for (int p = 0; p < 3; p++) {
        uint32_t abp = sb + ((p == 2) ? 16384 : 0);
        uint32_t bbp = sb + 32768 + ((p == 1) ? 32768 : 0);
        #pragma unroll
        for (int ks = 0; ks < 4; ks++) {
            uint32_t a[2][4];
            #pragma unroll
            for (int mt = 0; mt < 2; mt++)
                ldsm_x4(a[mt][0], a[mt][1], a[mt][2], a[mt][3],
                        abp + sw128(a_roff + mt * 16 * 128 + ks * 32));
            #pragma unroll
            for (int bp = 0; bp < 8; bp++) {
                uint32_t b0, b1, b2, b3;
                ldsm_x4(b0, b1, b2, b3, bbp + sw128(b_roff + bp * 16 * 128 + ks * 32));
                #pragma unroll
                for (int mt = 0; mt < 2; mt++) {
                    mma16816(accS[mt][2 * bp],     a[mt], b0, b1);
                    mma16816(accS[mt][2 * bp + 1], a[mt], b2, b3);
                }
            }
        }
    }
    __syncthreads();   // qp/kp smem now reusable

    // ---- phase 2: softmax (alpha folded into exp) ----
    float* red = (float*)(ab + 65536);   // 2 x 128 floats
    float rmax[2][2];
    #pragma unroll
    for (int mt = 0; mt < 2; mt++)
        #pragma unroll
        for (int rr = 0; rr < 2; rr++) {
            float m = -1e30f;
            #pragma unroll
            for (int nt = 0; nt < 16; nt++)
                m = fmaxf(m, fmaxf(accS[mt][nt][2 * rr], accS[mt][nt][2 * rr + 1]));
            m = fmaxf(m, __shfl_xor_sync(0xffffffffu, m, 1));
            m = fmaxf(m, __shfl_xor_sync(0xffffffffu, m, 2));
            int rowl = wm * 32 + mt * 16 + rr * 8 + (lane >> 2);
            if ((lane & 3) == 0) red[wn * 128 + rowl] = m;
        }
    __syncthreads();
    #pragma unroll
    for (int mt = 0; mt < 2; mt++)
        #pragma unroll
        for (int rr = 0; rr < 2; rr++) {
            int rowl = wm * 32 + mt * 16 + rr * 8 + (lane >> 2);
            rmax[mt][rr] = fmaxf(red[rowl], red[128 + rowl]);
        }
    __syncthreads();
    #pragma unroll
    for (int mt = 0; mt < 2; mt++)
        #pragma unroll
        for (int rr = 0; rr < 2; rr++) {
            float m = rmax[mt][rr], s = 0.f;
            #pragma unroll
            for (int nt = 0; nt < 16; nt++) {
                float e0 = __expf((accS[mt][nt][2 * rr]     - m) * 0.125f);
                float e1 = __expf((accS[mt][nt][2 * rr + 1] - m) * 0.125f);
                accS[mt][nt][2 * rr]     = e0;
                accS[mt][nt][2 * rr + 1] = e1;
                s += e0 + e1;
            }
            s += __shfl_xor_sync(0xffffffffu, s, 1);
            s += __shfl_xor_sync(0xffffffffu, s, 2);
            int rowl = wm * 32 + mt * 16 + rr * 8 + (lane >> 2);
            if ((lane & 3) == 0) red[wn * 128 + rowl] = s;
        }
    __syncthreads();

    // ---- normalize, round to fp16 ONCE; write AH (gmem) and P-tile (smem) ----
    #pragma unroll
    for (int mt = 0; mt < 2; mt++)
        #pragma unroll
        for (int rr = 0; rr < 2; rr++) {
            int rowl = wm * 32 + mt * 16 + rr * 8 + (lane >> 2);
            float inv = 1.f / (red[rowl] + red[128 + rowl]);
            size_t rbase = (size_t)z * (NN * NN) + (size_t)(bm + rowl) * NN
                         + wn * 128 + (lane & 3) * 2;
            #pragma unroll
            for (int nt = 0; nt < 16; nt++) {
                float p0 = accS[mt][nt][2 * rr]     * inv;
                float p1 = accS[mt][nt][2 * rr + 1] * inv;
                __half2 hv = __floats2half2_rn(p0, p1);
                *(__half2*)(AH + rbase + nt * 8) = hv;
                int col = wn * 128 + nt * 8 + (lane & 3) * 2;
                *(__half2*)(ab + (col >> 6) * 16384
                            + sw128((uint32_t)(rowl * 128 + (col & 63) * 2))) = hv;
            }
        }
    __syncthreads();

    // ---- phase 3: PV = P @ V (NP1), each warp owns full K, 32 n-cols ----
    float accPV[2][4][4];
    #pragma unroll
    for (int mt = 0; mt < 2; mt++)
        #pragma unroll
        for (int nt = 0; nt < 4; nt++)
            #pragma unroll
            for (int j = 0; j < 4; j++) accPV[mt][nt][j] = 0.f;

    const uint32_t pvb_roff = (uint32_t)((wn * 32 + ((lane >> 4) << 3) + (lane & 7)) * 128
                                         + (((lane >> 3) & 1) << 4));
    #pragma unroll
    for (int kc = 0; kc < 4; kc++) {
        uint32_t abase = sb + kc * 16384;
        uint32_t bbase = sb + 98304 + kc * 8192;
        #pragma unroll
        for (int ks = 0; ks < 4; ks++) {
            uint32_t a[2][4];
            #pragma unroll
            for (int mt = 0; mt < 2; mt++)
                ldsm_x4(a[mt][0], a[mt][1], a[mt][2], a[mt][3],
                        abase + sw128(a_roff + mt * 16 * 128 + ks * 32));
            #pragma unroll
            for (int bp = 0; bp < 2; bp++) {
                uint32_t b0, b1, b2, b3;
                ldsm_x4(b0, b1, b2, b3, bbase + sw128(pvb_roff + bp * 16 * 128 + ks * 32));
                #pragma unroll
                for (int mt = 0; mt < 2; mt++) {
                    mma16816(accPV[mt][2 * bp],     a[mt], b0, b1);
                    mma16816(accPV[mt][2 * bp + 1], a[mt], b2, b3);
                }
            }
        }
    }

    // ---- epilogue: ctx split2 ----
    #pragma unroll
    for (int mt = 0; mt < 2; mt++)
        #pragma unroll
        for (int rr = 0; rr < 2; rr++) {
            int rowl = wm * 32 + mt * 16 + rr * 8 + (lane >> 2);
            size_t cbase = (size_t)bt * NN * CB + (size_t)(bm + rowl) * CB
                         + (size_t)head * HDD + wn * 32 + (lane & 3) * 2;
            #pragma unroll
            for (int nt = 0; nt < 4; nt++) {
                float v0 = accPV[mt][nt][2 * rr];
                float v1 = accPV[mt][nt][2 * rr + 1];
                float h0 = hfr(v0), h1 = hfr(v1);
                *(__half2*)(cxh + cbase + nt * 8) = __floats2half2_rn(h0, h1);
                *(__half2*)(cxl + cbase + nt * 8) = __floats2half2_rn(v0 - h0, v1 - h1);
            }
        }
}

// ---------------- weight split / round ----------------
__global__ void wsplit_kernel(const float* __restrict__ w, __half* __restrict__ h,
                              __half* __restrict__ l, int n) {
    int i = blockIdx.x * 256 + threadIdx.x;
    if (i >= n) return;
    float a  = w[i];
    float hh = hfr(a);
    h[i] = __float2half_rn(hh);
    l[i] = __float2half_rn(a - hh);
}
__global__ void wround_kernel(const float* __restrict__ w, __half* __restrict__ h, int n) {
    int i = blockIdx.x * 256 + threadIdx.x;
    if (i >= n) return;
    h[i] = __float2half_rn(w[i]);
}

// ---------------- transpose + split (vw -> vwT splits) ----------------
__global__ void tsplit_kernel(const float* __restrict__ w,
                              __half* __restrict__ th, __half* __restrict__ tl) {
    __shared__ float tile[32][33];
    int bx = blockIdx.x * 32, by = blockIdx.y * 32;
    int tx = threadIdx.x & 31, ty = threadIdx.x >> 5;
    #pragma unroll
    for (int i = 0; i < 4; i++)
        tile[ty + i * 8][tx] = w[(size_t)(by + ty + i * 8) * CB + bx + tx];
    __syncthreads();
    #pragma unroll
    for (int i = 0; i < 4; i++) {
        int orow = bx + ty + i * 8;
        float a = tile[tx][ty + i * 8];
        float h = hfr(a);
        th[(size_t)orow * CB + by + tx] = __float2half_rn(h);
        tl[(size_t)orow * CB + by + tx] = __float2half_rn(a - h);
    }
}

// ---------------- bc = wv @ v_b + bv ----------------
__global__ void bc_kernel(const float* __restrict__ wv, const float* __restrict__ vb,
                          const float* __restrict__ bv, float* __restrict__ bc) {
    int d = blockIdx.x * 8 + (threadIdx.x >> 5);
    int lane = threadIdx.x & 31;
    const float* wr = wv + (size_t)d * CB;
    float s = 0.f;
    for (int k = lane * 4; k < CB; k += 128) {
        float4 w = *(const float4*)(wr + k);
        float4 v = *(const float4*)(vb + k);
        s += w.x * v.x + w.y * v.y + w.z * v.z + w.w * v.w;
    }
    #pragma unroll
    for (int off = 16; off > 0; off >>= 1) s += __shfl_xor_sync(0xffffffffu, s, off);
    if (lane == 0) bc[d] = s + bv[d];
}

// ---------------- x round + q/k splits (scale fused, packed arrays) ----------------
__global__ void qk_split_kernel(const float* __restrict__ x) {
    size_t idx = (size_t)blockIdx.x * 256 + threadIdx.x;
    size_t row = idx >> 8;
    int c4 = (int)(idx & 255) * 4;
    int srow = (int)(((row >> 12) << 8) | (row & 255));
    float4 xv = *(const float4*)(x + row * CB + c4);
    float4 qs = *(const float4*)(g_qscale + (size_t)srow * CB + c4);
    float4 ks = *(const float4*)(g_kscale + (size_t)srow * CB + c4);
    size_t base = row * CB + c4;

    float xi[4] = {xv.x, xv.y, xv.z, xv.w};
    float qi[4] = {xv.x * qs.x, xv.y * qs.y, xv.z * qs.z, xv.w * qs.w};
    float ki[4] = {xv.x * ks.x, xv.y * ks.y, xv.z * ks.z, xv.w * ks.w};

    __half xh[4], qh[4], ql[4], kh[4], kl[4];
    #pragma unroll
    for (int j = 0; j < 4; j++) {
        xh[j] = __float2half_rn(xi[j]);
        float h;
        h = hfr(qi[j]); qh[j] = __float2half_rn(h); ql[j] = __float2half_rn(qi[j] - h);
        h = hfr(ki[j]); kh[j] = __float2half_rn(h); kl[j] = __float2half_rn(ki[j] - h);
    }
    *(uint2*)(g_xh + base) = *(uint2*)xh;
    *(uint2*)(g_qkh + base)      = *(uint2*)qh;  *(uint2*)(g_qkl + base)      = *(uint2*)ql;
    *(uint2*)(g_qkh + QK + base) = *(uint2*)kh;  *(uint2*)(g_qkl + QK + base) = *(uint2*)kl;
}

// ---------------- expert sums ----------------
__global__ void expert_sum_kernel(const float* __restrict__ qe, const float* __restrict__ ke) {
    int c = blockIdx.x * 256 + threadIdx.x;
    int k = blockIdx.y;
    const float* src = blockIdx.z ? ke : qe;
    float* dst = blockIdx.z ? g_ksum : g_qsum;
    const float* p = src + (size_t)k * CB * CB + c;
    float s = 0.f;
    #pragma unroll 4
    for (int r = 0; r < CB; r++) s += p[(size_t)r * CB];
    dst[k * CB + c] = s;
}

// ---------------- dyn softmax ----------------
__global__ void dyn_kernel(const float* __restrict__ y, const float* __restrict__ dw,
                           const float* __restrict__ db) {
    int row  = blockIdx.x * 8 + (threadIdx.x >> 5);
    int lane = threadIdx.x & 31;
    const float* yr = y + (size_t)row * CB;
    float acc[KEXP];
    #pragma unroll
    for (int j = 0; j < KEXP; j++) acc[j] = 0.f;
    for (int c = lane * 4; c < CB; c += 128) {
        float4 yv = *(const float4*)(yr + c);
        #pragma unroll
        for (int j = 0; j < KEXP; j++) {
            float4 w = *(const float4*)(dw + j * CB + c);
            acc[j] += yv.x * w.x + yv.y * w.y + yv.z * w.z + yv.w * w.w;
        }
    }
    #pragma unroll
    for (int j = 0; j < KEXP; j++)
        #pragma unroll
        for (int off = 16; off > 0; off >>= 1)
            acc[j] += __shfl_xor_sync(0xffffffffu, acc[j], off);
    if (lane == 0) {
        float l[KEXP], m = -1e30f;
        #pragma unroll
        for (int j = 0; j < KEXP; j++) { l[j] = acc[j] + db[j]; m = fmaxf(m, l[j]); }
        float s = 0.f;
        #pragma unroll
        for (int j = 0; j < KEXP; j++) { l[j] = expf(l[j] - m); s += l[j]; }
        float inv = 1.f / s;
        #pragma unroll
        for (int j = 0; j < KEXP; j++) g_dyn[row * KEXP + j] = l[j] * inv;
    }
}

// ---------------- q/k scales ----------------
__global__ void scale_kernel() {
    int c  = blockIdx.x * 256 + threadIdx.x;
    int bn = blockIdx.y;
    const float* d = g_dyn + bn * KEXP;
    float qs = 0.f, ks = 0.f;
    #pragma unroll
    for (int j = 0; j < KEXP; j++) {
        float dj = d[j];
        qs += dj * g_qsum[j * CB + c];
        ks += dj * g_ksum[j * CB + c];
    }
    g_qscale[(size_t)bn * CB + c] = qs;
    g_kscale[(size_t)bn * CB + c] = ks;
}

// ---------------- attn_avg (half2 vectorized) ----------------
__global__ void attn_avg_kernel(const __half* __restrict__ AH, float* __restrict__ out2) {
    size_t e = ((size_t)blockIdx.x * 256 + threadIdx.x) * 2;
    size_t bt  = e >> 16;
    size_t rem = e & 65535;
    size_t base = bt * ((size_t)HH * NN * NN) + rem;
    float s0 = 0.f, s1 = 0.f;
    #pragma unroll
    for (int h = 0; h < HH; h++) {
        __half2 v = *(const __half2*)(AH + base + (size_t)h * NN * NN);
        float2 f = __half22float2(v);
        s0 += f.x; s1 += f.y;
    }
    *(float2*)(out2 + e) = make_float2(s0 * (1.f / HH), s1 * (1.f / HH));
}

// ---------------- LayerNorm ----------------
__device__ __forceinline__ float block_sum(float v) {
    __shared__ float sh[8];
    int lane = threadIdx.x & 31, w = threadIdx.x >> 5;
    #pragma unroll
    for (int off = 16; off > 0; off >>= 1) v += __shfl_xor_sync(0xffffffffu, v, off);
    if (lane == 0) sh[w] = v;
    __syncthreads();
    float t = (threadIdx.x < 8) ? sh[threadIdx.x] : 0.f;
    if (w == 0) {
        #pragma unroll
        for (int off = 4; off > 0; off >>= 1) t += __shfl_xor_sync(0xffffffffu, t, off);
        if (lane == 0) sh[0] = t;
    }
    __syncthreads();
    float r = sh[0];
    __syncthreads();
    return r;
}

__global__ void ln_kernel(float* __restrict__ h, const float* __restrict__ gamma,
                          const float* __restrict__ beta) {
    int row = blockIdx.x;
    float* p = h + (size_t)row * CB;
    float4 v = ((float4*)p)[threadIdx.x];
    float mu = block_sum(v.x + v.y + v.z + v.w) * (1.f / CB);
    float d0 = v.x - mu, d1 = v.y - mu, d2 = v.z - mu, d3 = v.w - mu;
    float var = block_sum(d0 * d0 + d1 * d1 + d2 * d2 + d3 * d3) * (1.f / CB);
    float inv = rsqrtf(var + EPS);
    float4 g  = ((const float4*)gamma)[threadIdx.x];
    float4 be = ((const float4*)beta)[threadIdx.x];
    float4 o;
    o.x = d0 * inv * g.x + be.x;
    o.y = d1 * inv * g.y + be.y;
    o.z = d2 * inv * g.z + be.z;
    o.w = d3 * inv * g.w + be.w;
    ((float4*)p)[threadIdx.x] = o;
}

// ---------------- launch ----------------
extern "C" void kernel_launch(void* const* d_in, const int* in_sizes, int n_in,
                              void* d_out, int out_size) {
    const float* x    = (const float*)d_in[0];
    const float* y    = (const float*)d_in[1];
    const float* q_ex = (const float*)d_in[3];
    const float* k_ex = (const float*)d_in[4];
    const float* dynw = (const float*)d_in[5];
    const float* dynb = (const float*)d_in[6];
    const float* v_w  = (const float*)d_in[7];
    const float* v_b  = (const float*)d_in[8];
    const float* in_w = (const float*)d_in[9];
    const float* in_b = (const float*)d_in[10];
    const float* o_w  = (const float*)d_in[11];
    const float* o_b  = (const float*)d_in[12];
    const float* gam  = (const float*)d_in[13];
    const float* bet  = (const float*)d_in[14];

    float* out1 = (float*)d_out;
    float* out2 = out1 + (size_t)MROWS * CB;

    #define SYM(T, v, s) T* v; cudaGetSymbolAddress((void**)&v, s);
    SYM(float, p_bc, g_bc)
    SYM(__half, p_xh, g_xh)
    SYM(__half, p_qkh, g_qkh)   SYM(__half, p_qkl, g_qkl)
    SYM(__half, p_qpkh, g_qpkh) SYM(__half, p_qpkl, g_qpkl)
    SYM(__half, p_vpth, g_vpth)
    SYM(__half, p_cxh, g_cxh)   SYM(__half, p_cxl, g_cxl)
    SYM(__half, p_ah, g_ah)
    SYM(__half, pw_qkh, w_qkh)  SYM(__half, pw_qkl, w_qkl)
    SYM(__half, pw_wvh, w_wvh)  SYM(__half, pw_wvl, w_wvl)
    SYM(__half, pw_vwth, w_vwth) SYM(__half, pw_vwtl, w_vwtl)
    SYM(__half, pw_wch, w_wch)  SYM(__half, pw_wcl, w_wcl)
    SYM(__half, pw_owh, w_owh)
    #undef SYM

    const int SM_NP3 = 256 + 3 * (4 * 16384);   // 196864
    const int SM_NP2 = 256 + 3 * (3 * 16384);   // 147712
    const int SM_FL  = 256 + 131072;            // 131328
    cudaFuncSetAttribute(hmma_f16<3,0>, cudaFuncAttributeMaxDynamicSharedMemorySize, SM_NP3);
    cudaFuncSetAttribute(hmma_f16<2,0>, cudaFuncAttributeMaxDynamicSharedMemorySize, SM_NP2);
    cudaFuncSetAttribute(hmma_f16<2,2>, cudaFuncAttributeMaxDynamicSharedMemorySize, SM_NP2);
    cudaFuncSetAttribute(flash_kernel,  cudaFuncAttributeMaxDynamicSharedMemorySize, SM_FL);

    // ---- prep ----
    expert_sum_kernel<<<dim3(CB / 256, KEXP, 2), 256>>>(q_ex, k_ex);
    dyn_kernel<<<(BB * NN) / 8, 256>>>(y, dynw, dynb);
    scale_kernel<<<dim3(CB / 256, BB * NN), 256>>>();

    const int WNi = CB * CB;
    wsplit_kernel<<<2 * WNi / 256, 256>>>(in_w, pw_qkh, pw_qkl, 2 * WNi);           // wq + wk
    wsplit_kernel<<<WNi / 256, 256>>>(in_w + 2 * WNS, pw_wvh, pw_wvl, WNi);         // wv
    wround_kernel<<<WNi / 256, 256>>>(o_w, pw_owh, WNi);
    tsplit_kernel<<<dim3(32, 32), 256>>>(v_w, pw_vwth, pw_vwtl);
    bc_kernel<<<CB / 8, 256>>>(in_w + 2 * WNS, v_b, in_b + 2 * CB, p_bc);
    qk_split_kernel<<<(int)(QK / 4 / 256), 256>>>(x);

    // ---- Wc = wv @ vw (split2) ----
    hmma_f16<3,0><<<dim3(8, 8), 256, SM_NP3>>>(
        pw_wvh, pw_wvl, pw_vwth, pw_vwtl, nullptr, pw_wch, pw_wcl,
        CB, CB, CB, CB, nullptr, nullptr, 0, 0);

    // ---- vpT = Wc @ x^T + bc (OMODE2) ----
    hmma_f16<2,2><<<dim3(256, 8), 256, SM_NP2>>>(
        pw_wch, pw_wcl, p_xh, nullptr, nullptr, p_vpth, nullptr,
        CB, CB, CB, CB, p_bc, nullptr, 0, 0);

    // ---- qp & kp in ONE dual-batch NP3 launch ----
    hmma_f16<3,0><<<dim3(8, 256, 2), 256, SM_NP3>>>(
        p_qkh, p_qkl, pw_qkh, pw_qkl, nullptr, p_qpkh, p_qpkl,
        CB, CB, CB, CB, in_b, nullptr, QK, WNS);

    // ---- flash attention ----
    flash_kernel<<<dim3(2, BTT * HH), 256, SM_FL>>>(
        p_qpkh, p_qpkl, p_qpkh + QK, p_qpkl + QK, p_vpth, p_ah, p_cxh, p_cxl);

    // ---- attn_avg ----
    attn_avg_kernel<<<(BTT * NN * NN / 2) / 256, 256>>>(p_ah, out2);

    // ---- h = x + ctx @ out_w^T + out_b ----
    hmma_f16<2,0><<<dim3(8, 256), 256, SM_NP2>>>(
        p_cxh, p_cxl, pw_owh, nullptr, out1, nullptr, nullptr,
        CB, CB, CB, CB, o_b, x, 0, 0);
    // ---- LayerNorm in-place ----
    ln_kernel<<<MROWS, 256>>>(out1, gam, bet);
}

// round 10
// speedup vs baseline: 1.1984x; 1.1984x over previous
#include <cuda_runtime.h>
#include <cuda_fp16.h>
#include <math.h>
#include <stddef.h>
#include <stdint.h>

// ---------------- problem constants ----------------
constexpr int BB   = 8;
constexpr int TT   = 16;
constexpr int NN   = 256;
constexpr int CB   = 1024;
constexpr int HH   = 16;
constexpr int HDD  = 64;
constexpr int KEXP = 8;
constexpr int BTT  = BB * TT;          // 128
constexpr int MROWS = BTT * NN;        // 32768
constexpr float EPS = 1e-5f;
constexpr size_t QK  = (size_t)MROWS * CB;
constexpr size_t WNS = (size_t)CB * CB;

// ---------------- device scratch ----------------
__device__ __align__(128) float g_qsum[KEXP * CB];
__device__ __align__(128) float g_ksum[KEXP * CB];
__device__ __align__(128) float g_dyn[BB * NN * KEXP];
__device__ __align__(128) float g_qscale[BB * NN * CB];
__device__ __align__(128) float g_kscale[BB * NN * CB];
__device__ __align__(128) float g_bc[CB];

__device__ __align__(128) __half g_xh  [QK];
__device__ __align__(128) __half g_qkh [2 * QK];      // q then k (scaled splits)
__device__ __align__(128) __half g_qkl [2 * QK];
__device__ __align__(128) __half g_qpkh[2 * QK];      // qp then kp
__device__ __align__(128) __half g_qpkl[2 * QK];
__device__ __align__(128) __half g_vpth[QK];          // vp transposed per bt: [bt][d][key]
__device__ __align__(128) __half g_cxh [QK];          // ctx single fp16
__device__ __align__(128) __half g_ah  [(size_t)BTT * HH * NN * NN];   // probs fp16

__device__ __align__(128) __half w_qkh [2 * WNS];     // wq,wk splits
__device__ __align__(128) __half w_qkl [2 * WNS];
__device__ __align__(128) __half w_wvh [WNS];
__device__ __align__(128) __half w_wvl [WNS];
__device__ __align__(128) __half w_vwth[WNS];
__device__ __align__(128) __half w_vwtl[WNS];
__device__ __align__(128) __half w_wch [WNS];         // Wc rounded single
__device__ __align__(128) __half w_owh [WNS];

// ---------------- helpers ----------------
__device__ __forceinline__ uint32_t smem_u32(const void* p) {
    return (uint32_t)__cvta_generic_to_shared(p);
}
__device__ __forceinline__ uint32_t sw128(uint32_t o) { return o ^ ((o >> 3) & 0x70); }
__device__ __forceinline__ float hfr(float a) { return __half2float(__float2half_rn(a)); }
__device__ __forceinline__ uint32_t packh2(float a, float b) {
    __half2 t = __floats2half2_rn(a, b);
    return *(uint32_t*)&t;
}
__device__ __forceinline__ void ldsm_x4(uint32_t& r0, uint32_t& r1, uint32_t& r2, uint32_t& r3,
                                        uint32_t addr) {
    asm volatile("ldmatrix.sync.aligned.m8n8.x4.shared.b16 {%0,%1,%2,%3}, [%4];"
                 : "=r"(r0), "=r"(r1), "=r"(r2), "=r"(r3) : "r"(addr));
}
__device__ __forceinline__ void mma16816(float* d, const uint32_t* a, uint32_t b0, uint32_t b1) {
    asm volatile("mma.sync.aligned.m16n8k16.row.col.f32.f16.f16.f32 "
                 "{%0,%1,%2,%3}, {%4,%5,%6,%7}, {%8,%9}, {%0,%1,%2,%3};"
                 : "+f"(d[0]), "+f"(d[1]), "+f"(d[2]), "+f"(d[3])
                 : "r"(a[0]), "r"(a[1]), "r"(a[2]), "r"(a[3]), "r"(b0), "r"(b1));
}
__device__ __forceinline__ void cp16(uint32_t dst, const void* src) {
    asm volatile("cp.async.cg.shared.global [%0], [%1], 16;" :: "r"(dst), "l"(src) : "memory");
}
__device__ __forceinline__ void cp_commit() { asm volatile("cp.async.commit_group;" ::: "memory"); }
template<int N> __device__ __forceinline__ void cp_wait() {
    asm volatile("cp.async.wait_group %0;" :: "n"(N) : "memory");
}

// ---------------- fp16 split HMMA GEMM (plain NT), 3-stage cp.async pipeline ----------------
// NPROD=3: (A0+A1)@(B0+B1) via hh,hl,lh.  NPROD=2: (A0+A1)@B0.  NPROD=1: A0@B0.
// OMODE 0: row-major out (Cf fp32 / Ch+Cl split2 / Ch single), bias per COL, optional resid.
//          gridDim.z batching with strides az (A,C), bz (B), bias += z*CB.
// OMODE 2: vpT write — out[col>>8][row][col&255] half (Ch only), bias per ROW.
template<int NPROD, int OMODE>
__global__ void __launch_bounds__(256, NPROD == 1 ? 2 : 1)
hmma_f16(const __half* __restrict__ A0, const __half* __restrict__ A1,
         const __half* __restrict__ B0, const __half* __restrict__ B1,
         float* __restrict__ Cf, __half* __restrict__ Ch, __half* __restrict__ Cl,
         int Kdim, int lda, int ldb, int ldc,
         const float* __restrict__ bias, const float* __restrict__ resid,
         size_t az, size_t bz)
{
    constexpr int NSA = (NPROD >= 2) ? 2 : 1;
    constexpr int NSB = (NPROD == 3) ? 2 : 1;
    constexpr int ATILE = 128 * 64 * 2;
    constexpr int BTILE = 128 * 64 * 2;
    constexpr int STAGE = NSA * ATILE + NSB * BTILE;

    extern __shared__ char dsm[];
    const uint32_t sraw  = smem_u32(dsm);
    const uint32_t sbase = (sraw + 127u) & ~127u;

    const int tid  = threadIdx.x;
    const int wid  = tid >> 5;
    const int lane = tid & 31;
    const int wm   = wid & 3;
    const int wn   = wid >> 2;

    if (OMODE == 0 && blockIdx.z) {
        size_t zo = blockIdx.z * az, zb = blockIdx.z * bz;
        A0 += zo; if (A1) A1 += zo;
        B0 += zb; if (B1) B1 += zb;
        if (Cf) Cf += zo;
        if (Ch) { Ch += zo; if (Cl) Cl += zo; }
        if (bias) bias += blockIdx.z * CB;
    }

    const __half* Ap[2] = {A0, A1};
    const __half* Bp[2] = {B0, B1};
    const int bm = blockIdx.y * 128, bn = blockIdx.x * 128;

    auto issue = [&](int s, int kt) {
        uint32_t st = sbase + s * STAGE;
        #pragma unroll
        for (int p = 0; p < NSA; p++) {
            const __half* As = Ap[p];
            #pragma unroll
            for (int r = 0; r < 4; r++) {
                int i = tid + r * 256;
                int row = i >> 3, ch = (i & 7) * 16;
                cp16(st + p * ATILE + sw128((uint32_t)(row * 128 + ch)),
                     (const char*)(As + (size_t)(bm + row) * lda + kt) + ch);
            }
        }
        #pragma unroll
        for (int p = 0; p < NSB; p++) {
            const __half* Bs = Bp[p];
            #pragma unroll
            for (int r = 0; r < 4; r++) {
                int i = tid + r * 256;
                int row = i >> 3, ch = (i & 7) * 16;
                cp16(st + NSA * ATILE + p * BTILE + sw128((uint32_t)(row * 128 + ch)),
                     (const char*)(Bs + (size_t)(bn + row) * ldb + kt) + ch);
            }
        }
        cp_commit();
    };

    float acc[2][8][4];
    #pragma unroll
    for (int mt = 0; mt < 2; mt++)
        #pragma unroll
        for (int nt = 0; nt < 8; nt++)
            #pragma unroll
            for (int j = 0; j < 4; j++) acc[mt][nt][j] = 0.f;

    const uint32_t a_roff = (uint32_t)((wm * 32 + (lane & 15)) * 128 + ((lane >> 4) << 4));
    const uint32_t b_roff = (uint32_t)((wn * 64 + ((lane >> 4) << 3) + (lane & 7)) * 128
                                       + (((lane >> 3) & 1) << 4));

    auto compute = [&](int s) {
        uint32_t st = sbase + s * STAGE;
        #pragma unroll
        for (int p = 0; p < NPROD; p++) {
            int pa, pb;
            if (NPROD == 3)      { pa = (p == 2) ? 1 : 0; pb = (p == 1) ? 1 : 0; }
            else if (NPROD == 2) { pa = p; pb = 0; }
            else                 { pa = 0; pb = 0; }
            uint32_t abp = st + pa * ATILE;
            uint32_t bbp = st + NSA * ATILE + pb * BTILE;
            #pragma unroll
            for (int ks = 0; ks < 4; ks++) {
                uint32_t a[2][4];
                #pragma unroll
                for (int mt = 0; mt < 2; mt++)
                    ldsm_x4(a[mt][0], a[mt][1], a[mt][2], a[mt][3],
                            abp + sw128(a_roff + mt * 16 * 128 + ks * 32));
                #pragma unroll
                for (int bp = 0; bp < 4; bp++) {
                    uint32_t b0, b1, b2, b3;
                    ldsm_x4(b0, b1, b2, b3, bbp + sw128(b_roff + bp * 16 * 128 + ks * 32));
                    #pragma unroll
                    for (int mt = 0; mt < 2; mt++) {
                        mma16816(acc[mt][2 * bp],     a[mt], b0, b1);
                        mma16816(acc[mt][2 * bp + 1], a[mt], b2, b3);
                    }
                }
            }
        }
    };

    const int nch = Kdim / 64;
    issue(0, 0);
    if (nch > 1) issue(1, 64);
    if (nch > 2) issue(2, 128);
    for (int t = 0; t < nch; t++) {
        int rem = nch - 1 - t;
        if (rem >= 2) cp_wait<2>();
        else if (rem == 1) cp_wait<1>();
        else cp_wait<0>();
        __syncthreads();
        compute(t % 3);
        __syncthreads();
        if (t + 3 < nch) issue(t % 3, (t + 3) * 64);
    }

    // ---- epilogue ----
    #pragma unroll
    for (int mt = 0; mt < 2; mt++) {
        int r0 = bm + wm * 32 + mt * 16 + (lane >> 2);
        #pragma unroll
        for (int nt = 0; nt < 8; nt++) {
            int col = bn + wn * 64 + nt * 8 + (lane & 3) * 2;
            #pragma unroll
            for (int rr = 0; rr < 2; rr++) {
                int row = r0 + rr * 8;
                float v0 = acc[mt][nt][2 * rr];
                float v1 = acc[mt][nt][2 * rr + 1];
                if (OMODE == 2) {
                    float b = bias[row];
                    v0 += b; v1 += b;
                    size_t t0 = (size_t)(col >> 8) * (CB * NN) + (size_t)row * NN + (col & 255);
                    *(__half2*)(Ch + t0) = __floats2half2_rn(v0, v1);
                } else {
                    if (bias)  { v0 += bias[col]; v1 += bias[col + 1]; }
                    if (resid) {
                        const float* rp = resid + (size_t)row * ldc + col;
                        v0 += rp[0]; v1 += rp[1];
                    }
                    size_t base = (size_t)row * ldc + col;
                    if (Cf) *(float2*)(Cf + base) = make_float2(v0, v1);
                    if (Ch && Cl) {
                        float h0 = hfr(v0), h1 = hfr(v1);
                        *(__half2*)(Ch + base) = __floats2half2_rn(h0, h1);
                        *(__half2*)(Cl + base) = __floats2half2_rn(v0 - h0, v1 - h1);
                    } else if (Ch) {
                        *(__half2*)(Ch + base) = __floats2half2_rn(v0, v1);
                    }
                }
            }
        }
    }
}

// ---------------- flash attention (R8 structure, NP1 PV, ctx single fp16) ----------------
// grid (2 m-blocks, BT*H). 128 q-rows x 256 keys x 64 hd.
__global__ void __launch_bounds__(256)
flash_kernel(const __half* __restrict__ qph, const __half* __restrict__ qpl,
             const __half* __restrict__ kph, const __half* __restrict__ kpl,
             const __half* __restrict__ vpt,
             __half* __restrict__ AH, __half* __restrict__ cxh)
{
    // smem: [0,32K) qp splits | [32K,96K) kp splits | [96K,128K) V 4 chunks
    // reuse [0,..) after scores: red[2x128] f32, then sred 128x66 f32
    extern __shared__ char dsm[];
    const uint32_t sraw = smem_u32(dsm);
    const uint32_t sb   = (sraw + 127u) & ~127u;
    char* const ab      = dsm + (sb - sraw);

    const int tid = threadIdx.x, wid = tid >> 5, lane = tid & 31;
    const int wm = wid & 3, wn = wid >> 2;
    const int z = blockIdx.y;
    const int bt = z >> 4, head = z & 15;
    const int bm = blockIdx.x * 128;

    const size_t qoff = (size_t)bt * NN * CB + (size_t)head * HDD;
    const size_t voff = (size_t)bt * CB * NN + (size_t)head * HDD * NN;

    // ---- load all operands ----
    {
        const __half* qs[2] = {qph, qpl};
        #pragma unroll
        for (int p = 0; p < 2; p++)
            #pragma unroll
            for (int r = 0; r < 4; r++) {
                int i = tid + r * 256;
                int row = i >> 3, ch = (i & 7) * 16;
                cp16(sb + p * 16384 + sw128((uint32_t)(row * 128 + ch)),
                     (const char*)(qs[p] + qoff + (size_t)(bm + row) * CB) + ch);
            }
        const __half* ks[2] = {kph, kpl};
        #pragma unroll
        for (int p = 0; p < 2; p++)
            #pragma unroll
            for (int r = 0; r < 8; r++) {
                int i = tid + r * 256;
                int row = i >> 3, ch = (i & 7) * 16;
                cp16(sb + 32768 + p * 32768 + sw128((uint32_t)(row * 128 + ch)),
                     (const char*)(ks[p] + qoff + (size_t)row * CB) + ch);
            }
        #pragma unroll
        for (int c = 0; c < 4; c++)
            #pragma unroll
            for (int r = 0; r < 2; r++) {
                int i = tid + r * 256;
                int row = i >> 3, ch = (i & 7) * 16;
                cp16(sb + 98304 + c * 8192 + sw128((uint32_t)(row * 128 + ch)),
                     (const char*)(vpt + voff + (size_t)row * NN + c * 64) + ch);
            }
        cp_commit();
        cp_wait<0>();
        __syncthreads();
    }

    // ---- scores: S = qp @ kp^T (NP3 on splits), 128 x 256 ----
    float accS[2][16][4];
    #pragma unroll
    for (int mt = 0; mt < 2; mt++)
        #pragma unroll
        for (int nt = 0; nt < 16; nt++)
            #pragma unroll
            for (int j = 0; j < 4; j++) accS[mt][nt][j] = 0.f;

    const uint32_t a_roff = (uint32_t)((wm * 32 + (lane & 15)) * 128 + ((lane >> 4) << 4));
    const uint32_t b_roff = (uint32_t)((wn * 128 + ((lane >> 4) << 3) + (lane & 7)) * 128
                                       + (((lane >> 3) & 1) << 4));
    #pragma unroll
    for (int p = 0; p < 3; p++) {
        uint32_t abp = sb + ((p == 2) ? 16384 : 0);
        uint32_t bbp = sb + 32768 + ((p == 1) ? 32768 : 0);
        #pragma unroll
        for (int ks = 0; ks < 4; ks++) {
            uint32_t a[2][4];
            #pragma unroll
            for (int mt = 0; mt < 2; mt++)
                ldsm_x4(a[mt][0], a[mt][1], a[mt][2], a[mt][3],
                        abp + sw128(a_roff + mt * 16 * 128 + ks * 32));
            #pragma unroll
            for (int bp = 0; bp < 8; bp++) {
                uint32_t b0, b1, b2, b3;
                ldsm_x4(b0, b1, b2, b3, bbp + sw128(b_roff + bp * 16 * 128 + ks * 32));
                #pragma unroll
                for (int mt = 0; mt < 2; mt++) {
                    mma16816(accS[mt][2 * bp],     a[mt], b0, b1);
                    mma16816(accS[mt][2 * bp + 1], a[mt], b2, b3);
                }
            }
        }
    }
    __syncthreads();   // qp/kp smem free

    // ---- softmax (alpha folded into exp) ----
    float* red = (float*)ab;   // 2 x 128 floats
    float rmax[2][2];
    #pragma unroll
    for (int mt = 0; mt < 2; mt++)
        #pragma unroll
        for (int rr = 0; rr < 2; rr++) {
            float m = -1e30f;
            #pragma unroll
            for (int nt = 0; nt < 16; nt++)
                m = fmaxf(m, fmaxf(accS[mt][nt][2 * rr], accS[mt][nt][2 * rr + 1]));
            m = fmaxf(m, __shfl_xor_sync(0xffffffffu, m, 1));
            m = fmaxf(m, __shfl_xor_sync(0xffffffffu, m, 2));
            int rowl = wm * 32 + mt * 16 + rr * 8 + (lane >> 2);
            if ((lane & 3) == 0) red[wn * 128 + rowl] = m;
        }
    __syncthreads();
    #pragma unroll
    for (int mt = 0; mt < 2; mt++)
        #pragma unroll
        for (int rr = 0; rr < 2; rr++) {
            int rowl = wm * 32 + mt * 16 + rr * 8 + (lane >> 2);
            rmax[mt][rr] = fmaxf(red[rowl], red[128 + rowl]);
        }
    __syncthreads();
    #pragma unroll
    for (int mt = 0; mt < 2; mt++)
        #pragma unroll
        for (int rr = 0; rr < 2; rr++) {
            float m = rmax[mt][rr], s = 0.f;
            #pragma unroll
            for (int nt = 0; nt < 16; nt++) {
                float e0 = __expf((accS[mt][nt][2 * rr]     - m) * 0.125f);
                float e1 = __expf((accS[mt][nt][2 * rr + 1] - m) * 0.125f);
                accS[mt][nt][2 * rr]     = e0;
                accS[mt][nt][2 * rr + 1] = e1;
                s += e0 + e1;
            }
            s += __shfl_xor_sync(0xffffffffu, s, 1);
            s += __shfl_xor_sync(0xffffffffu, s, 2);
            int rowl = wm * 32 + mt * 16 + rr * 8 + (lane >> 2);
            if ((lane & 3) == 0) red[wn * 128 + rowl] = s;
        }
    __syncthreads();
    #pragma unroll
    for (int mt = 0; mt < 2; mt++)
        #pragma unroll
        for (int rr = 0; rr < 2; rr++) {
            int rowl = wm * 32 + mt * 16 + rr * 8 + (lane >> 2);
            float inv = 1.f / (red[rowl] + red[128 + rowl]);
            #pragma unroll
            for (int nt = 0; nt < 16; nt++) {
                accS[mt][nt][2 * rr]     *= inv;
                accS[mt][nt][2 * rr + 1] *= inv;
            }
        }

    // ---- write probs (fp16) for attn_avg ----
    #pragma unroll
    for (int mt = 0; mt < 2; mt++)
        #pragma unroll
        for (int rr = 0; rr < 2; rr++) {
            int rowl = wm * 32 + mt * 16 + rr * 8 + (lane >> 2);
            size_t rbase = (size_t)z * (NN * NN) + (size_t)(bm + rowl) * NN
                         + wn * 128 + (lane & 3) * 2;
            #pragma unroll
            for (int nt = 0; nt < 16; nt++)
                *(__half2*)(AH + rbase + nt * 8) =
                    __floats2half2_rn(accS[mt][nt][2 * rr], accS[mt][nt][2 * rr + 1]);
        }

    // ---- PV: ctx = P_hi @ V (NP1, rounded probs) ----
    float accPV[2][8][4];
    #pragma unroll
    for (int mt = 0; mt < 2; mt++)
        #pragma unroll
        for (int nt = 0; nt < 8; nt++)
            #pragma unroll
            for (int j = 0; j < 4; j++) accPV[mt][nt][j] = 0.f;

    const uint32_t pvb_roff = (uint32_t)((((lane >> 4) << 3) + (lane & 7)) * 128
                                         + (((lane >> 3) & 1) << 4));
    #pragma unroll
    for (int g = 0; g < 8; g++) {
        int cglob = wn * 2 + (g >> 2);
        int ksl = g & 3;
        uint32_t bbase = sb + 98304 + cglob * 8192;
        uint32_t aph[2][4];
        #pragma unroll
        for (int mt = 0; mt < 2; mt++) {
            #pragma unroll
            for (int t2 = 0; t2 < 2; t2++) {
                int tile = 2 * g + t2;
                aph[mt][2 * t2]     = packh2(accS[mt][tile][0], accS[mt][tile][1]);
                aph[mt][2 * t2 + 1] = packh2(accS[mt][tile][2], accS[mt][tile][3]);
            }
        }
        #pragma unroll
        for (int bp = 0; bp < 4; bp++) {
            uint32_t b0, b1, b2, b3;
            ldsm_x4(b0, b1, b2, b3, bbase + sw128(pvb_roff + bp * 16 * 128 + ksl * 32));
            #pragma unroll
            for (int mt = 0; mt < 2; mt++) {
                mma16816(accPV[mt][2 * bp],     aph[mt], b0, b1);
                mma16816(accPV[mt][2 * bp + 1], aph[mt], b2, b3);
            }
        }
    }

    // ---- cross-warp (wn) reduction of PV partials, write ctx single fp16 ----
    __syncthreads();
    float* sred = (float*)ab;   // 128 x 66
    if (wn == 0) {
        #pragma unroll
        for (int mt = 0; mt < 2; mt++)
            #pragma unroll
            for (int rr = 0; rr < 2; rr++) {
                int rowl = wm * 32 + mt * 16 + rr * 8 + (lane >> 2);
                #pragma unroll
                for (int nt = 0; nt < 8; nt++) {
                    int col = nt * 8 + (lane & 3) * 2;
                    *(float2*)(sred + rowl * 66 + col) =
                        make_float2(accPV[mt][nt][2 * rr], accPV[mt][nt][2 * rr + 1]);
                }
            }
    }
    __syncthreads();
    if (wn == 1) {
        #pragma unroll
        for (int mt = 0; mt < 2; mt++)
            #pragma unroll
            for (int rr = 0; rr < 2; rr++) {
                int rowl = wm * 32 + mt * 16 + rr * 8 + (lane >> 2);
                size_t cbase = (size_t)bt * NN * CB + (size_t)(bm + rowl) * CB
                             + (size_t)head * HDD;
                #pragma unroll
                for (int nt = 0; nt < 8; nt++) {
                    int col = nt * 8 + (lane & 3) * 2;
                    float2 o = *(float2*)(sred + rowl * 66 + col);
                    float v0 = accPV[mt][nt][2 * rr]     + o.x;
                    float v1 = accPV[mt][nt][2 * rr + 1] + o.y;
                    *(__half2*)(cxh + cbase + col) = __floats2half2_rn(v0, v1);
                }
            }
    }
}

// ---------------- weight split / round ----------------
__global__ void wsplit_kernel(const float* __restrict__ w, __half* __restrict__ h,
                              __half* __restrict__ l, int n) {
    int i = blockIdx.x * 256 + threadIdx.x;
    if (i >= n) return;
    float a  = w[i];
    float hh = hfr(a);
    h[i] = __float2half_rn(hh);
    l[i] = __float2half_rn(a - hh);
}
__global__ void wround_kernel(const float* __restrict__ w, __half* __restrict__ h, int n) {
    int i = blockIdx.x * 256 + threadIdx.x;
    if (i >= n) return;
    h[i] = __float2half_rn(w[i]);
}

// ---------------- transpose + split (vw -> vwT splits) ----------------
__global__ void tsplit_kernel(const float* __restrict__ w,
                              __half* __restrict__ th, __half* __restrict__ tl) {
    __shared__ float tile[32][33];
    int bx = blockIdx.x * 32, by = blockIdx.y * 32;
    int tx = threadIdx.x & 31, ty = threadIdx.x >> 5;
    #pragma unroll
    for (int i = 0; i < 4; i++)
        tile[ty + i * 8][tx] = w[(size_t)(by + ty + i * 8) * CB + bx + tx];
    __syncthreads();
    #pragma unroll
    for (int i = 0; i < 4; i++) {
        int orow = bx + ty + i * 8;
        float a = tile[tx][ty + i * 8];
        float h = hfr(a);
        th[(size_t)orow * CB + by + tx] = __float2half_rn(h);
        tl[(size_t)orow * CB + by + tx] = __float2half_rn(a - h);
    }
}

// ---------------- bc = wv @ v_b + bv ----------------
__global__ void bc_kernel(const float* __restrict__ wv, const float* __restrict__ vb,
                          const float* __restrict__ bv, float* __restrict__ bc) {
    int d = blockIdx.x * 8 + (threadIdx.x >> 5);
    int lane = threadIdx.x & 31;
    const float* wr = wv + (size_t)d * CB;
    float s = 0.f;
    for (int k = lane * 4; k < CB; k += 128) {
        float4 w = *(const float4*)(wr + k);
        float4 v = *(const float4*)(vb + k);
        s += w.x * v.x + w.y * v.y + w.z * v.z + w.w * v.w;
    }
    #pragma unroll
    for (int off = 16; off > 0; off >>= 1) s += __shfl_xor_sync(0xffffffffu, s, off);
    if (lane == 0) bc[d] = s + bv[d];
}

// ---------------- x round + q/k splits (scale fused, packed arrays) ----------------
__global__ void qk_split_kernel(const float* __restrict__ x) {
    size_t idx = (size_t)blockIdx.x * 256 + threadIdx.x;
    size_t row = idx >> 8;
    int c4 = (int)(idx & 255) * 4;
    int srow = (int)(((row >> 12) << 8) | (row & 255));
    float4 xv = *(const float4*)(x + row * CB + c4);
    float4 qs = *(const float4*)(g_qscale + (size_t)srow * CB + c4);
    float4 ks = *(const float4*)(g_kscale + (size_t)srow * CB + c4);
    size_t base = row * CB + c4;

    float xi[4] = {xv.x, xv.y, xv.z, xv.w};
    float qi[4] = {xv.x * qs.x, xv.y * qs.y, xv.z * qs.z, xv.w * qs.w};
    float ki[4] = {xv.x * ks.x, xv.y * ks.y, xv.z * ks.z, xv.w * ks.w};

    __half xh[4], qh[4], ql[4], kh[4], kl[4];
    #pragma unroll
    for (int j = 0; j < 4; j++) {
        xh[j] = __float2half_rn(xi[j]);
        float h;
        h = hfr(qi[j]); qh[j] = __float2half_rn(h); ql[j] = __float2half_rn(qi[j] - h);
        h = hfr(ki[j]); kh[j] = __float2half_rn(h); kl[j] = __float2half_rn(ki[j] - h);
    }
    *(uint2*)(g_xh + base) = *(uint2*)xh;
    *(uint2*)(g_qkh + base)      = *(uint2*)qh;  *(uint2*)(g_qkl + base)      = *(uint2*)ql;
    *(uint2*)(g_qkh + QK + base) = *(uint2*)kh;  *(uint2*)(g_qkl + QK + base) = *(uint2*)kl;
}

// ---------------- expert sums ----------------
__global__ void expert_sum_kernel(const float* __restrict__ qe, const float* __restrict__ ke) {
    int c = blockIdx.x * 256 + threadIdx.x;
    int k = blockIdx.y;
    const float* src = blockIdx.z ? ke : qe;
    float* dst = blockIdx.z ? g_ksum : g_qsum;
    const float* p = src + (size_t)k * CB * CB + c;
    float s = 0.f;
    #pragma unroll 4
    for (int r = 0; r < CB; r++) s += p[(size_t)r * CB];
    dst[k * CB + c] = s;
}

// ---------------- dyn softmax ----------------
__global__ void dyn_kernel(const float* __restrict__ y, const float* __restrict__ dw,
                           const float* __restrict__ db) {
    int row  = blockIdx.x * 8 + (threadIdx.x >> 5);
    int lane = threadIdx.x & 31;
    const float* yr = y + (size_t)row * CB;
    float acc[KEXP];
    #pragma unroll
    for (int j = 0; j < KEXP; j++) acc[j] = 0.f;
    for (int c = lane * 4; c < CB; c += 128) {
        float4 yv = *(const float4*)(yr + c);
        #pragma unroll
        for (int j = 0; j < KEXP; j++) {
            float4 w = *(const float4*)(dw + j * CB + c);
            acc[j] += yv.x * w.x + yv.y * w.y + yv.z * w.z + yv.w * w.w;
        }
    }
    #pragma unroll
    for (int j = 0; j < KEXP; j++)
        #pragma unroll
        for (int off = 16; off > 0; off >>= 1)
            acc[j] += __shfl_xor_sync(0xffffffffu, acc[j], off);
    if (lane == 0) {
        float l[KEXP], m = -1e30f;
        #pragma unroll
        for (int j = 0; j < KEXP; j++) { l[j] = acc[j] + db[j]; m = fmaxf(m, l[j]); }
        float s = 0.f;
        #pragma unroll
        for (int j = 0; j < KEXP; j++) { l[j] = expf(l[j] - m); s += l[j]; }
        float inv = 1.f / s;
        #pragma unroll
        for (int j = 0; j < KEXP; j++) g_dyn[row * KEXP + j] = l[j] * inv;
    }
}

// ---------------- q/k scales ----------------
__global__ void scale_kernel() {
    int c  = blockIdx.x * 256 + threadIdx.x;
    int bn = blockIdx.y;
    const float* d = g_dyn + bn * KEXP;
    float qs = 0.f, ks = 0.f;
    #pragma unroll
    for (int j = 0; j < KEXP; j++) {
        float dj = d[j];
        qs += dj * g_qsum[j * CB + c];
        ks += dj * g_ksum[j * CB + c];
    }
    g_qscale[(size_t)bn * CB + c] = qs;
    g_kscale[(size_t)bn * CB + c] = ks;
}

// ---------------- attn_avg (half2 vectorized) ----------------
__global__ void attn_avg_kernel(const __half* __restrict__ AH, float* __restrict__ out2) {
    size_t e = ((size_t)blockIdx.x * 256 + threadIdx.x) * 2;
    size_t bt  = e >> 16;
    size_t rem = e & 65535;
    size_t base = bt * ((size_t)HH * NN * NN) + rem;
    float s0 = 0.f, s1 = 0.f;
    #pragma unroll
    for (int h = 0; h < HH; h++) {
        __half2 v = *(const __half2*)(AH + base + (size_t)h * NN * NN);
        float2 f = __half22float2(v);
        s0 += f.x; s1 += f.y;
    }
    *(float2*)(out2 + e) = make_float2(s0 * (1.f / HH), s1 * (1.f / HH));
}

// ---------------- LayerNorm ----------------
__device__ __forceinline__ float block_sum(float v) {
    __shared__ float sh[8];
    int lane = threadIdx.x & 31, w = threadIdx.x >> 5;
    #pragma unroll
    for (int off = 16; off > 0; off >>= 1) v += __shfl_xor_sync(0xffffffffu, v, off);
    if (lane == 0) sh[w] = v;
    __syncthreads();
    float t = (threadIdx.x < 8) ? sh[threadIdx.x] : 0.f;
    if (w == 0) {
        #pragma unroll
        for (int off = 4; off > 0; off >>= 1) t += __shfl_xor_sync(0xffffffffu, t, off);
        if (lane == 0) sh[0] = t;
    }
    __syncthreads();
    float r = sh[0];
    __syncthreads();
    return r;
}

__global__ void ln_kernel(float* __restrict__ h, const float* __restrict__ gamma,
                          const float* __restrict__ beta) {
    int row = blockIdx.x;
    float* p = h + (size_t)row * CB;
    float4 v = ((float4*)p)[threadIdx.x];
    float mu = block_sum(v.x + v.y + v.z + v.w) * (1.f / CB);
    float d0 = v.x - mu, d1 = v.y - mu, d2 = v.z - mu, d3 = v.w - mu;
    float var = block_sum(d0 * d0 + d1 * d1 + d2 * d2 + d3 * d3) * (1.f / CB);
    float inv = rsqrtf(var + EPS);
    float4 g  = ((const float4*)gamma)[threadIdx.x];
    float4 be = ((const float4*)beta)[threadIdx.x];
    float4 o;
    o.x = d0 * inv * g.x + be.x;
    o.y = d1 * inv * g.y + be.y;
    o.z = d2 * inv * g.z + be.z;
    o.w = d3 * inv * g.w + be.w;
    ((float4*)p)[threadIdx.x] = o;
}

// ---------------- launch ----------------
extern "C" void kernel_launch(void* const* d_in, const int* in_sizes, int n_in,
                              void* d_out, int out_size) {
    const float* x    = (const float*)d_in[0];
    const float* y    = (const float*)d_in[1];
    const float* q_ex = (const float*)d_in[3];
    const float* k_ex = (const float*)d_in[4];
    const float* dynw = (const float*)d_in[5];
    const float* dynb = (const float*)d_in[6];
    const float* v_w  = (const float*)d_in[7];
    const float* v_b  = (const float*)d_in[8];
    const float* in_w = (const float*)d_in[9];
    const float* in_b = (const float*)d_in[10];
    const float* o_w  = (const float*)d_in[11];
    const float* o_b  = (const float*)d_in[12];
    const float* gam  = (const float*)d_in[13];
    const float* bet  = (const float*)d_in[14];

    float* out1 = (float*)d_out;
    float* out2 = out1 + (size_t)MROWS * CB;

    #define SYM(T, v, s) T* v; cudaGetSymbolAddress((void**)&v, s);
    SYM(float, p_bc, g_bc)
    SYM(__half, p_xh, g_xh)
    SYM(__half, p_qkh, g_qkh)   SYM(__half, p_qkl, g_qkl)
    SYM(__half, p_qpkh, g_qpkh) SYM(__half, p_qpkl, g_qpkl)
    SYM(__half, p_vpth, g_vpth)
    SYM(__half, p_cxh, g_cxh)
    SYM(__half, p_ah, g_ah)
    SYM(__half, pw_qkh, w_qkh)  SYM(__half, pw_qkl, w_qkl)
    SYM(__half, pw_wvh, w_wvh)  SYM(__half, pw_wvl, w_wvl)
    SYM(__half, pw_vwth, w_vwth) SYM(__half, pw_vwtl, w_vwtl)
    SYM(__half, pw_wch, w_wch)
    SYM(__half, pw_owh, w_owh)
    #undef SYM

    const int SM_NP3 = 256 + 3 * (4 * 16384);   // 196864
    const int SM_NP1 = 256 + 3 * (2 * 16384);   //  98560
    const int SM_FL  = 256 + 131072;            // 131328
    cudaFuncSetAttribute(hmma_f16<3,0>, cudaFuncAttributeMaxDynamicSharedMemorySize, SM_NP3);
    cudaFuncSetAttribute(hmma_f16<1,0>, cudaFuncAttributeMaxDynamicSharedMemorySize, SM_NP1);
    cudaFuncSetAttribute(hmma_f16<1,2>, cudaFuncAttributeMaxDynamicSharedMemorySize, SM_NP1);
    cudaFuncSetAttribute(flash_kernel,  cudaFuncAttributeMaxDynamicSharedMemorySize, SM_FL);

    // ---- prep ----
    expert_sum_kernel<<<dim3(CB / 256, KEXP, 2), 256>>>(q_ex, k_ex);
    dyn_kernel<<<(BB * NN) / 8, 256>>>(y, dynw, dynb);
    scale_kernel<<<dim3(CB / 256, BB * NN), 256>>>();

    const int WNi = CB * CB;
    wsplit_kernel<<<2 * WNi / 256, 256>>>(in_w, pw_qkh, pw_qkl, 2 * WNi);       // wq + wk
    wsplit_kernel<<<WNi / 256, 256>>>(in_w + 2 * WNS, pw_wvh, pw_wvl, WNi);     // wv
    wround_kernel<<<WNi / 256, 256>>>(o_w, pw_owh, WNi);
    tsplit_kernel<<<dim3(32, 32), 256>>>(v_w, pw_vwth, pw_vwtl);
    bc_kernel<<<CB / 8, 256>>>(in_w + 2 * WNS, v_b, in_b + 2 * CB, p_bc);
    qk_split_kernel<<<(int)(QK / 4 / 256), 256>>>(x);

    // ---- Wc = wv @ vw (NP3, rounded single output) ----
    hmma_f16<3,0><<<dim3(8, 8), 256, SM_NP3>>>(
        pw_wvh, pw_wvl, pw_vwth, pw_vwtl, nullptr, pw_wch, nullptr,
        CB, CB, CB, CB, nullptr, nullptr, 0, 0);

    // ---- vpT = Wc @ x^T + bc (NP1, OMODE2) ----
    hmma_f16<1,2><<<dim3(256, 8), 256, SM_NP1>>>(
        pw_wch, nullptr, p_xh, nullptr, nullptr, p_vpth, nullptr,
        CB, CB, CB, CB, p_bc, nullptr, 0, 0);

    // ---- qp & kp in ONE dual-batch NP3 launch ----
    hmma_f16<3,0><<<dim3(8, 256, 2), 256, SM_NP3>>>(
        p_qkh, p_qkl, pw_qkh, pw_qkl, nullptr, p_qpkh, p_qpkl,
        CB, CB, CB, CB, in_b, nullptr, QK, WNS);

    // ---- flash attention ----
    flash_kernel<<<dim3(2, BTT * HH), 256, SM_FL>>>(
        p_qpkh, p_qpkl, p_qpkh + QK, p_qpkl + QK, p_vpth, p_ah, p_cxh);

    // ---- attn_avg ----
    attn_avg_kernel<<<(BTT * NN * NN / 2) / 256, 256>>>(p_ah, out2);

    // ---- h = x + ctx @ out_w^T + out_b (NP1) ----
    hmma_f16<1,0><<<dim3(8, 256), 256, SM_NP1>>>(
        p_cxh, nullptr, pw_owh, nullptr, out1, nullptr, nullptr,
        CB, CB, CB, CB, o_b, x, 0, 0);
    // ---- LayerNorm in-place ----
    ln_kernel<<<MROWS, 256>>>(out1, gam, bet);
}